// round 1
// baseline (speedup 1.0000x reference)
#include <cuda_runtime.h>
#include <math.h>

// Problem constants
#define Bb   2
#define Ss   4096
#define Hh   16
#define KHh  4
#define HDd  128
#define Dd   2048   // H*HD
#define KVD  512    // KH*HD
#define Ww   512
#define NROW (Bb*Ss) // 8192 token rows

// ---------------- scratch (device globals; no allocation in kernel_launch) ---
__device__ float g_xn [NROW*Dd];     // 64 MB
__device__ float g_q  [NROW*Dd];     // 64 MB
__device__ float g_k  [NROW*KVD];    // 16 MB
__device__ float g_v  [NROW*KVD];    // 16 MB
__device__ float g_att[NROW*Dd];     // 64 MB
__device__ float g_cos[Ss*(HDd/2)];
__device__ float g_sin[Ss*(HDd/2)];

// ---------------- RMSNorm: one block per token row ---------------------------
__global__ __launch_bounds__(256) void rms_kernel(const float* __restrict__ x,
                                                  const float* __restrict__ w) {
    int row = blockIdx.x;
    int t = threadIdx.x;
    const float4* xr = (const float4*)(x + (size_t)row * Dd);
    const float4* wr = (const float4*)w;
    float4* yr = (float4*)(g_xn + (size_t)row * Dd);

    float4 v0 = xr[t];
    float4 v1 = xr[t + 256];
    float ss = v0.x*v0.x + v0.y*v0.y + v0.z*v0.z + v0.w*v0.w
             + v1.x*v1.x + v1.y*v1.y + v1.z*v1.z + v1.w*v1.w;
    #pragma unroll
    for (int o = 16; o; o >>= 1) ss += __shfl_xor_sync(0xffffffffu, ss, o);

    __shared__ float wsum[8];
    __shared__ float tot;
    if ((t & 31) == 0) wsum[t >> 5] = ss;
    __syncthreads();
    if (t == 0) {
        float s2 = 0.f;
        #pragma unroll
        for (int i = 0; i < 8; i++) s2 += wsum[i];
        tot = s2;
    }
    __syncthreads();
    float scale = 1.0f / sqrtf(tot * (1.0f / Dd) + 1e-6f);

    float4 w0 = wr[t], w1 = wr[t + 256];
    float4 o0, o1;
    o0.x = v0.x * scale * w0.x; o0.y = v0.y * scale * w0.y;
    o0.z = v0.z * scale * w0.z; o0.w = v0.w * scale * w0.w;
    o1.x = v1.x * scale * w1.x; o1.y = v1.y * scale * w1.y;
    o1.z = v1.z * scale * w1.z; o1.w = v1.w * scale * w1.w;
    yr[t] = o0; yr[t + 256] = o1;
}

// ---------------- SGEMM 128x128x8, 256 threads, 8x8 microtiles ---------------
// C[M,N] = A[M,K] @ B[K,N], all row-major, M/N multiples of 128, K of 8.
__global__ __launch_bounds__(256) void sgemm_kernel(const float* __restrict__ A,
                                                    const float* __restrict__ Bm,
                                                    float* __restrict__ C,
                                                    int N, int K) {
    __shared__ float As[8][128];   // As[k][m] (transposed store)
    __shared__ float Bs[8][128];   // Bs[k][n]
    int t  = threadIdx.x;
    int tx = t & 15, ty = t >> 4;
    int bm = blockIdx.y << 7, bn = blockIdx.x << 7;

    int arow = t >> 1;            // 0..127
    int acol = (t & 1) << 2;      // 0 or 4
    int brow = t >> 5;            // 0..7
    int bcol = (t & 31) << 2;     // 0..124

    const float* Ap = A  + (size_t)(bm + arow) * K + acol;
    const float* Bp = Bm + (size_t)brow * N + bn + bcol;

    float acc[8][8];
    #pragma unroll
    for (int i = 0; i < 8; i++)
        #pragma unroll
        for (int j = 0; j < 8; j++) acc[i][j] = 0.f;

    for (int k0 = 0; k0 < K; k0 += 8) {
        float4 av = *(const float4*)Ap;
        float4 bv = *(const float4*)Bp;
        Ap += 8;
        Bp += (size_t)8 * N;
        __syncthreads();
        As[acol + 0][arow] = av.x;
        As[acol + 1][arow] = av.y;
        As[acol + 2][arow] = av.z;
        As[acol + 3][arow] = av.w;
        *(float4*)&Bs[brow][bcol] = bv;
        __syncthreads();
        #pragma unroll
        for (int kk = 0; kk < 8; kk++) {
            float a[8], b[8];
            *(float4*)&a[0] = *(float4*)&As[kk][ty << 2];
            *(float4*)&a[4] = *(float4*)&As[kk][64 + (ty << 2)];
            *(float4*)&b[0] = *(float4*)&Bs[kk][tx << 2];
            *(float4*)&b[4] = *(float4*)&Bs[kk][64 + (tx << 2)];
            #pragma unroll
            for (int i = 0; i < 8; i++)
                #pragma unroll
                for (int j = 0; j < 8; j++)
                    acc[i][j] += a[i] * b[j];
        }
    }
    #pragma unroll
    for (int i = 0; i < 8; i++) {
        int m = (i < 4) ? ((ty << 2) + i) : (64 + (ty << 2) + i - 4);
        float* Cp = C + (size_t)(bm + m) * N + bn;
        float4 c0 = {acc[i][0], acc[i][1], acc[i][2], acc[i][3]};
        float4 c1 = {acc[i][4], acc[i][5], acc[i][6], acc[i][7]};
        *(float4*)(Cp + (tx << 2))      = c0;
        *(float4*)(Cp + 64 + (tx << 2)) = c1;
    }
}

// ---------------- RoPE table: fp32 angle exactly like reference, f64 trig ----
__global__ __launch_bounds__(256) void rope_table_kernel() {
    int idx = blockIdx.x * 256 + threadIdx.x;   // Ss*64 entries
    int s = idx >> 6;
    int j = idx & 63;
    float e = (float)(2 * j) * (1.0f / 128.0f);
    float p = powf(10000.0f, e);
    float inv = 1.0f / p;
    float ang = (float)s * inv;                 // fp32 angle, same as ref
    g_cos[idx] = (float)cos((double)ang);
    g_sin[idx] = (float)sin((double)ang);
}

__global__ __launch_bounds__(256) void rope_apply_kernel(float* __restrict__ t, int nh) {
    int idx = blockIdx.x * 256 + threadIdx.x;
    int j = idx & 63;
    int r = idx >> 6;                // ((b*S+s)*nh + h)
    int s = (r / nh) & (Ss - 1);
    float2* p = (float2*)t + (size_t)r * 64 + j;
    float2 v = *p;
    float c  = g_cos[(s << 6) + j];
    float sn = g_sin[(s << 6) + j];
    float2 o;
    o.x = v.x * c - v.y * sn;
    o.y = v.x * sn + v.y * c;
    *p = o;
}

// ---------------- Flash-style sliding-window attention -----------------------
// Block = (64 queries) x (one head) x (one batch). Key chunks of 64 over the
// window [s0-512, s0+63]; chunk starts are 64-aligned so negative chunks are
// skipped wholesale. valid key: 0 <= (sq - kg) <= 512.
#define STR 132
#define ATT_SMEM ((2*64*STR + 64*64 + 3*64) * 4)

__global__ __launch_bounds__(256) void attn_kernel() {
    extern __shared__ float sm[];
    float* Qs = sm;                 // [64][132]
    float* KV = sm + 64 * STR;      // [64][132] (K then V)
    float* Ps = sm + 2 * 64 * STR;  // [64][64]
    float* Mr = Ps + 64 * 64;
    float* Lr = Mr + 64;
    float* Al = Lr + 64;

    int t  = threadIdx.x;
    int tx = t & 15, ty = t >> 4;
    int b = blockIdx.z, h = blockIdx.y;
    int s0 = blockIdx.x << 6;
    int kh = h >> 2;                // GQA: 4 q-heads per kv-head

    const float* qb = g_q + ((size_t)((b * Ss + s0) * Hh + h)) * HDd;
    #pragma unroll
    for (int it = 0; it < 8; ++it) {
        int idx = t + (it << 8);
        int row = idx >> 5, d4 = (idx & 31) << 2;
        *(float4*)&Qs[row * STR + d4] =
            *(const float4*)(qb + (size_t)row * (Hh * HDd) + d4);
    }
    if (t < 64) { Mr[t] = -3.0e38f; Lr[t] = 0.0f; }

    float o[4][8];
    #pragma unroll
    for (int i = 0; i < 4; i++)
        #pragma unroll
        for (int dd = 0; dd < 8; dd++) o[i][dd] = 0.f;
    __syncthreads();

    const float SCALE = 0.08838834764831845f; // 1/sqrt(128)

    for (int c = 0; c < 9; ++c) {
        int cs = s0 - Ww + (c << 6);
        if (cs < 0) continue;

        // load K chunk
        const float* kb = g_k + ((size_t)((b * Ss + cs) * KHh + kh)) * HDd;
        #pragma unroll
        for (int it = 0; it < 8; ++it) {
            int idx = t + (it << 8);
            int row = idx >> 5, d4 = (idx & 31) << 2;
            *(float4*)&KV[row * STR + d4] =
                *(const float4*)(kb + (size_t)row * (KHh * HDd) + d4);
        }
        __syncthreads();

        // scores: rows ty+16i, cols tx+16j (strided mapping -> <=2-way LDS conflicts)
        float sc[4][4];
        #pragma unroll
        for (int i = 0; i < 4; i++)
            #pragma unroll
            for (int j = 0; j < 4; j++) sc[i][j] = 0.f;
        #pragma unroll 4
        for (int d = 0; d < 128; ++d) {
            float aq[4], bk[4];
            #pragma unroll
            for (int i = 0; i < 4; i++) aq[i] = Qs[(ty + (i << 4)) * STR + d];
            #pragma unroll
            for (int j = 0; j < 4; j++) bk[j] = KV[(tx + (j << 4)) * STR + d];
            #pragma unroll
            for (int i = 0; i < 4; i++)
                #pragma unroll
                for (int j = 0; j < 4; j++)
                    sc[i][j] += aq[i] * bk[j];
        }
        #pragma unroll
        for (int i = 0; i < 4; i++)
            #pragma unroll
            for (int j = 0; j < 4; j++) {
                int r = ty + (i << 4), ci = tx + (j << 4);
                int del = (s0 + r) - (cs + ci);
                Ps[(r << 6) + ci] =
                    (del >= 0 && del <= Ww) ? sc[i][j] * SCALE : -1.0e30f;
            }
        __syncthreads();

        // online softmax: 4 threads per row
        {
            int row = t >> 2, part = t & 3;
            float* pr = Ps + (row << 6) + (part << 4);
            float mx = -3.0e38f;
            #pragma unroll
            for (int q = 0; q < 16; q++) mx = fmaxf(mx, pr[q]);
            mx = fmaxf(mx, __shfl_xor_sync(0xffffffffu, mx, 1));
            mx = fmaxf(mx, __shfl_xor_sync(0xffffffffu, mx, 2));
            float mold = Mr[row];
            float mnew = fmaxf(mold, mx);
            float ssum = 0.f;
            #pragma unroll
            for (int q = 0; q < 16; q++) {
                float pv = expf(pr[q] - mnew);
                pr[q] = pv;
                ssum += pv;
            }
            ssum += __shfl_xor_sync(0xffffffffu, ssum, 1);
            ssum += __shfl_xor_sync(0xffffffffu, ssum, 2);
            if (part == 0) {
                float al = expf(mold - mnew);   // 0 on first valid chunk
                Mr[row] = mnew;
                Lr[row] = Lr[row] * al + ssum;
                Al[row] = al;
            }
        }
        __syncthreads();

        // load V chunk over KV
        const float* vb = g_v + ((size_t)((b * Ss + cs) * KHh + kh)) * HDd;
        #pragma unroll
        for (int it = 0; it < 8; ++it) {
            int idx = t + (it << 8);
            int row = idx >> 5, d4 = (idx & 31) << 2;
            *(float4*)&KV[row * STR + d4] =
                *(const float4*)(vb + (size_t)row * (KHh * HDd) + d4);
        }
        __syncthreads();

        // O = O*alpha + P @ V  (thread owns rows ty+16i, dims tx*8..tx*8+7)
        float alv[4];
        #pragma unroll
        for (int i = 0; i < 4; i++) alv[i] = Al[ty + (i << 4)];
        #pragma unroll
        for (int i = 0; i < 4; i++)
            #pragma unroll
            for (int dd = 0; dd < 8; dd++) o[i][dd] *= alv[i];
        #pragma unroll 2
        for (int j = 0; j < 64; ++j) {
            float pv[4];
            #pragma unroll
            for (int i = 0; i < 4; i++) pv[i] = Ps[((ty + (i << 4)) << 6) + j];
            float vv[8];
            *(float4*)&vv[0] = *(float4*)&KV[j * STR + (tx << 3)];
            *(float4*)&vv[4] = *(float4*)&KV[j * STR + (tx << 3) + 4];
            #pragma unroll
            for (int i = 0; i < 4; i++)
                #pragma unroll
                for (int dd = 0; dd < 8; dd++)
                    o[i][dd] += pv[i] * vv[dd];
        }
        __syncthreads();
    }

    // epilogue: divide by l, write (B,S,H*HD)
    #pragma unroll
    for (int i = 0; i < 4; i++) {
        int r = ty + (i << 4);
        float inv = 1.0f / Lr[r];
        float* ob = g_att + ((size_t)(b * Ss + s0 + r)) * Dd + (h << 7) + (tx << 3);
        float4 u0 = {o[i][0]*inv, o[i][1]*inv, o[i][2]*inv, o[i][3]*inv};
        float4 u1 = {o[i][4]*inv, o[i][5]*inv, o[i][6]*inv, o[i][7]*inv};
        *(float4*)ob       = u0;
        *(float4*)(ob + 4) = u1;
    }
}

// ---------------- host launcher ---------------------------------------------
extern "C" void kernel_launch(void* const* d_in, const int* in_sizes, int n_in,
                              void* d_out, int out_size) {
    (void)in_sizes; (void)n_in; (void)out_size;
    const float* x   = (const float*)d_in[0];
    const float* lnw = (const float*)d_in[1];
    const float* wq  = (const float*)d_in[2];
    const float* wk  = (const float*)d_in[3];
    const float* wv  = (const float*)d_in[4];
    const float* wo  = (const float*)d_in[5];
    float* out = (float*)d_out;

    void *pxn, *pq, *pk, *pv, *patt;
    cudaGetSymbolAddress(&pxn,  g_xn);
    cudaGetSymbolAddress(&pq,   g_q);
    cudaGetSymbolAddress(&pk,   g_k);
    cudaGetSymbolAddress(&pv,   g_v);
    cudaGetSymbolAddress(&patt, g_att);

    cudaFuncSetAttribute(attn_kernel,
                         cudaFuncAttributeMaxDynamicSharedMemorySize, ATT_SMEM);

    // 1) RMSNorm
    rms_kernel<<<NROW, 256>>>(x, lnw);
    // 2) Q/K/V projections
    sgemm_kernel<<<dim3(Dd / 128,  NROW / 128), 256>>>((const float*)pxn, wq, (float*)pq,  Dd,  Dd);
    sgemm_kernel<<<dim3(KVD / 128, NROW / 128), 256>>>((const float*)pxn, wk, (float*)pk,  KVD, Dd);
    sgemm_kernel<<<dim3(KVD / 128, NROW / 128), 256>>>((const float*)pxn, wv, (float*)pv,  KVD, Dd);
    // 3) RoPE
    rope_table_kernel<<<(Ss * 64) / 256, 256>>>();
    rope_apply_kernel<<<(Bb * Ss * Hh  * 64) / 256, 256>>>((float*)pq, Hh);
    rope_apply_kernel<<<(Bb * Ss * KHh * 64) / 256, 256>>>((float*)pk, KHh);
    // 4) Sliding-window attention
    attn_kernel<<<dim3(Ss / 64, Hh, Bb), 256, ATT_SMEM>>>();
    // 5) Output projection -> d_out
    sgemm_kernel<<<dim3(Dd / 128, NROW / 128), 256>>>((const float*)patt, wo, out, Dd, Dd);
}

// round 4
// speedup vs baseline: 1.7584x; 1.7584x over previous
#include <cuda_runtime.h>
#include <cuda_bf16.h>
#include <stdint.h>
#include <math.h>

// Problem constants
#define Bb   2
#define Ss   4096
#define Hh   16
#define KHh  4
#define HDd  128
#define Dd   2048   // H*HD
#define KVD  512    // KH*HD
#define Ww   512
#define NROW (Bb*Ss) // 8192 token rows

// ---------------- scratch (device globals; no allocation in kernel_launch) ---
__device__ float g_xn [NROW*Dd];
__device__ float g_q  [NROW*Dd];
__device__ float g_k  [NROW*KVD];
__device__ float g_v  [NROW*KVD];
__device__ float g_att[NROW*Dd];
__device__ float g_cos[Ss*(HDd/2)];
__device__ float g_sin[Ss*(HDd/2)];

// bf16x3 split scratch
__device__ __nv_bfloat16 g_xnh[NROW*Dd];
__device__ __nv_bfloat16 g_xnl[NROW*Dd];
__device__ __nv_bfloat16 g_ath[NROW*Dd];
__device__ __nv_bfloat16 g_atl[NROW*Dd];
__device__ __nv_bfloat16 g_wqh[Dd*Dd],  g_wql[Dd*Dd];    // [N,K] transposed
__device__ __nv_bfloat16 g_wkh[KVD*Dd], g_wkl[KVD*Dd];
__device__ __nv_bfloat16 g_wvh[KVD*Dd], g_wvl[KVD*Dd];
__device__ __nv_bfloat16 g_woh[Dd*Dd],  g_wol[Dd*Dd];

// ---------------- PTX helpers (compute_100-safe: cp.async + ldmatrix + mma) --
__device__ __forceinline__ uint32_t s2u(const void* p) {
    uint32_t a;
    asm("{ .reg .u64 t; cvta.to.shared.u64 t, %1; cvt.u32.u64 %0, t; }"
        : "=r"(a) : "l"(p));
    return a;
}
__device__ __forceinline__ void cpasync16(uint32_t s, const void* g) {
    asm volatile("cp.async.cg.shared.global [%0], [%1], 16;" :: "r"(s), "l"(g) : "memory");
}
#define CP_COMMIT()  asm volatile("cp.async.commit_group;" ::: "memory")
#define CP_WAIT(n)   asm volatile("cp.async.wait_group %0;" :: "n"(n) : "memory")

__device__ __forceinline__ void ldm_x4(uint32_t* r, uint32_t addr) {
    asm volatile("ldmatrix.sync.aligned.m8n8.x4.shared.b16 {%0,%1,%2,%3}, [%4];"
        : "=r"(r[0]), "=r"(r[1]), "=r"(r[2]), "=r"(r[3]) : "r"(addr));
}
__device__ __forceinline__ void mma_bf16(float* d, const uint32_t* a,
                                         uint32_t b0, uint32_t b1) {
    asm volatile(
        "mma.sync.aligned.m16n8k16.row.col.f32.bf16.bf16.f32 "
        "{%0,%1,%2,%3}, {%4,%5,%6,%7}, {%8,%9}, {%0,%1,%2,%3};"
        : "+f"(d[0]), "+f"(d[1]), "+f"(d[2]), "+f"(d[3])
        : "r"(a[0]), "r"(a[1]), "r"(a[2]), "r"(a[3]), "r"(b0), "r"(b1));
}

// ---------------- RMSNorm: one block per token row ---------------------------
__global__ __launch_bounds__(256) void rms_kernel(const float* __restrict__ x,
                                                  const float* __restrict__ w) {
    int row = blockIdx.x;
    int t = threadIdx.x;
    const float4* xr = (const float4*)(x + (size_t)row * Dd);
    const float4* wr = (const float4*)w;
    float4* yr = (float4*)(g_xn + (size_t)row * Dd);

    float4 v0 = xr[t];
    float4 v1 = xr[t + 256];
    float ss = v0.x*v0.x + v0.y*v0.y + v0.z*v0.z + v0.w*v0.w
             + v1.x*v1.x + v1.y*v1.y + v1.z*v1.z + v1.w*v1.w;
    #pragma unroll
    for (int o = 16; o; o >>= 1) ss += __shfl_xor_sync(0xffffffffu, ss, o);

    __shared__ float wsum[8];
    __shared__ float tot;
    if ((t & 31) == 0) wsum[t >> 5] = ss;
    __syncthreads();
    if (t == 0) {
        float s2 = 0.f;
        #pragma unroll
        for (int i = 0; i < 8; i++) s2 += wsum[i];
        tot = s2;
    }
    __syncthreads();
    float scale = 1.0f / sqrtf(tot * (1.0f / Dd) + 1e-6f);

    float4 w0 = wr[t], w1 = wr[t + 256];
    float4 o0, o1;
    o0.x = v0.x * scale * w0.x; o0.y = v0.y * scale * w0.y;
    o0.z = v0.z * scale * w0.z; o0.w = v0.w * scale * w0.w;
    o1.x = v1.x * scale * w1.x; o1.y = v1.y * scale * w1.y;
    o1.z = v1.z * scale * w1.z; o1.w = v1.w * scale * w1.w;
    yr[t] = o0; yr[t + 256] = o1;
}

// ---------------- bf16 split (hi/lo), same layout ----------------------------
__global__ __launch_bounds__(256) void split_kernel(const float* __restrict__ x,
                                                    __nv_bfloat16* __restrict__ hi,
                                                    __nv_bfloat16* __restrict__ lo) {
    int i = blockIdx.x * 256 + threadIdx.x;          // one float4 per thread
    float4 v = ((const float4*)x)[i];
    __nv_bfloat16 h0 = __float2bfloat16(v.x);
    __nv_bfloat16 h1 = __float2bfloat16(v.y);
    __nv_bfloat16 h2 = __float2bfloat16(v.z);
    __nv_bfloat16 h3 = __float2bfloat16(v.w);
    __nv_bfloat16 l0 = __float2bfloat16(v.x - __bfloat162float(h0));
    __nv_bfloat16 l1 = __float2bfloat16(v.y - __bfloat162float(h1));
    __nv_bfloat16 l2 = __float2bfloat16(v.z - __bfloat162float(h2));
    __nv_bfloat16 l3 = __float2bfloat16(v.w - __bfloat162float(h3));
    __nv_bfloat162* hp = (__nv_bfloat162*)hi;
    __nv_bfloat162* lp = (__nv_bfloat162*)lo;
    hp[2*i]   = __nv_bfloat162(h0, h1);
    hp[2*i+1] = __nv_bfloat162(h2, h3);
    lp[2*i]   = __nv_bfloat162(l0, l1);
    lp[2*i+1] = __nv_bfloat162(l2, l3);
}

// ---------------- weight split + transpose: W[K,N] -> T[N,K] hi/lo -----------
__global__ __launch_bounds__(256) void wsplitT_kernel(const float* __restrict__ W,
                                                      __nv_bfloat16* __restrict__ Th,
                                                      __nv_bfloat16* __restrict__ Tl,
                                                      int K, int N) {
    __shared__ float tile[32][33];
    int n0 = blockIdx.x << 5, k0 = blockIdx.y << 5;
    int tx = threadIdx.x & 31, ty = threadIdx.x >> 5;   // 32 x 8
    #pragma unroll
    for (int r = 0; r < 32; r += 8)
        tile[ty + r][tx] = W[(size_t)(k0 + ty + r) * N + n0 + tx];
    __syncthreads();
    #pragma unroll
    for (int r = 0; r < 32; r += 8) {
        int nrow = ty + r;
        float v = tile[tx][nrow];                       // W[k0+tx][n0+nrow]
        __nv_bfloat16 h = __float2bfloat16(v);
        size_t oi = (size_t)(n0 + nrow) * K + k0 + tx;
        Th[oi] = h;
        Tl[oi] = __float2bfloat16(v - __bfloat162float(h));
    }
}

// ---------------- mma.sync bf16x3 GEMM: C[M,N] = A @ B^T ---------------------
// A: [M,K] row-major hi/lo. B: [N,K] row-major hi/lo. Both K-major.
// CTA tile 128x128, BK=64 (one SW128 atom row per tile-row), 8 warps (64x32).
#define GBM 128
#define GBN 128
#define GBK 64
#define A_HI 0
#define A_LO 16384
#define B_HI 32768
#define B_LO 49152
#define GSTAGE 65536
#define GSMEM_TOTAL (2*GSTAGE)   // 128 KB

__device__ __forceinline__ void gemm_load_stage(uint32_t st,
        const __nv_bfloat16* Ah, const __nv_bfloat16* Al,
        const __nv_bfloat16* Bh, const __nv_bfloat16* Bl,
        int K, int t) {
    // A: 128 rows x 8 x 16B per matrix (1024 chunks; 4 per thread per matrix)
    #pragma unroll
    for (int i = 0; i < 4; i++) {
        int idx = t + (i << 8);
        int row = idx >> 3, kc = idx & 7;
        uint32_t off = (row << 7) + (kc << 4);
        uint32_t sw = off ^ ((off >> 3) & 0x70);
        cpasync16(st + A_HI + sw, Ah + (size_t)row * K + kc * 8);
        cpasync16(st + A_LO + sw, Al + (size_t)row * K + kc * 8);
    }
    // B: identical shape
    #pragma unroll
    for (int i = 0; i < 4; i++) {
        int idx = t + (i << 8);
        int row = idx >> 3, kc = idx & 7;
        uint32_t off = (row << 7) + (kc << 4);
        uint32_t sw = off ^ ((off >> 3) & 0x70);
        cpasync16(st + B_HI + sw, Bh + (size_t)row * K + kc * 8);
        cpasync16(st + B_LO + sw, Bl + (size_t)row * K + kc * 8);
    }
}

// per-lane ldmatrix address in a SW128 [128 rows x 128B] tile
__device__ __forceinline__ uint32_t ldaddr(uint32_t base, int row, int chunk, int lane) {
    int r = row + (lane & 15);
    int c = (chunk << 1) + (lane >> 4);
    uint32_t off = (r << 7) + (c << 4);
    return base + (off ^ ((off >> 3) & 0x70));
}

__global__ void __launch_bounds__(256, 1) gemm_bf16x3(
        const __nv_bfloat16* __restrict__ Ah, const __nv_bfloat16* __restrict__ Al,
        const __nv_bfloat16* __restrict__ Bh, const __nv_bfloat16* __restrict__ Bl,
        float* __restrict__ C, int Ncols, int K) {
    extern __shared__ char smem[];
    uint32_t sb = s2u(smem);
    int t = threadIdx.x;
    int lane = t & 31, wid = t >> 5;
    int bm = blockIdx.y << 7;
    int bn = blockIdx.x << 7;
    int wm = (wid >> 2) << 6;          // 0 or 64
    int wn = (wid & 3) << 5;           // 0,32,64,96

    const __nv_bfloat16* A0h = Ah + (size_t)bm * K;
    const __nv_bfloat16* A0l = Al + (size_t)bm * K;
    const __nv_bfloat16* B0h = Bh + (size_t)bn * K;
    const __nv_bfloat16* B0l = Bl + (size_t)bn * K;

    float acc[4][4][4];
    #pragma unroll
    for (int i = 0; i < 4; i++)
        #pragma unroll
        for (int j = 0; j < 4; j++)
            #pragma unroll
            for (int r = 0; r < 4; r++) acc[i][j][r] = 0.f;

    int NC = K / GBK;
    gemm_load_stage(sb, A0h, A0l, B0h, B0l, K, t);
    CP_COMMIT();

    for (int c = 0; c < NC; c++) {
        if (c + 1 < NC) {
            uint32_t stn = sb + (((c + 1) & 1) ? GSTAGE : 0);
            int ko = (c + 1) * GBK;
            gemm_load_stage(stn, A0h + ko, A0l + ko, B0h + ko, B0l + ko, K, t);
            CP_COMMIT();
            CP_WAIT(1);
        } else {
            CP_WAIT(0);
        }
        __syncthreads();

        uint32_t st = sb + ((c & 1) ? GSTAGE : 0);
        #pragma unroll
        for (int ks = 0; ks < 4; ks++) {
            uint32_t ah[4][4], al[4][4], bh[2][4], bl[2][4];
            #pragma unroll
            for (int mt = 0; mt < 4; mt++) {
                ldm_x4(ah[mt], ldaddr(st + A_HI, wm + mt * 16, ks, lane));
                ldm_x4(al[mt], ldaddr(st + A_LO, wm + mt * 16, ks, lane));
            }
            #pragma unroll
            for (int nt2 = 0; nt2 < 2; nt2++) {
                ldm_x4(bh[nt2], ldaddr(st + B_HI, wn + nt2 * 16, ks, lane));
                ldm_x4(bl[nt2], ldaddr(st + B_LO, wn + nt2 * 16, ks, lane));
            }
            #pragma unroll
            for (int mt = 0; mt < 4; mt++)
                #pragma unroll
                for (int nt = 0; nt < 4; nt++) {
                    int n2 = nt >> 1, hf = nt & 1;
                    // Ah*Bh + Ah*Bl + Al*Bh
                    mma_bf16(acc[mt][nt], ah[mt], bh[n2][hf], bh[n2][hf + 2]);
                    mma_bf16(acc[mt][nt], ah[mt], bl[n2][hf], bl[n2][hf + 2]);
                    mma_bf16(acc[mt][nt], al[mt], bh[n2][hf], bh[n2][hf + 2]);
                }
        }
        __syncthreads();
    }

    // epilogue: write fp32 C
    int gr = lane >> 2, gc = (lane & 3) << 1;
    #pragma unroll
    for (int mt = 0; mt < 4; mt++) {
        #pragma unroll
        for (int nt = 0; nt < 4; nt++) {
            int row0 = bm + wm + mt * 16 + gr;
            int col  = bn + wn + nt * 8 + gc;
            float2 v0 = {acc[mt][nt][0], acc[mt][nt][1]};
            float2 v1 = {acc[mt][nt][2], acc[mt][nt][3]};
            *(float2*)(C + (size_t)row0 * Ncols + col)       = v0;
            *(float2*)(C + (size_t)(row0 + 8) * Ncols + col) = v1;
        }
    }
}

// ---------------- RoPE table: fp32 angle exactly like reference, f64 trig ----
__global__ __launch_bounds__(256) void rope_table_kernel() {
    int idx = blockIdx.x * 256 + threadIdx.x;   // Ss*64 entries
    int s = idx >> 6;
    int j = idx & 63;
    float e = (float)(2 * j) * (1.0f / 128.0f);
    float p = powf(10000.0f, e);
    float inv = 1.0f / p;
    float ang = (float)s * inv;                 // fp32 angle, same as ref
    g_cos[idx] = (float)cos((double)ang);
    g_sin[idx] = (float)sin((double)ang);
}

__global__ __launch_bounds__(256) void rope_apply_kernel(float* __restrict__ t, int nh) {
    int idx = blockIdx.x * 256 + threadIdx.x;
    int j = idx & 63;
    int r = idx >> 6;                // ((b*S+s)*nh + h)
    int s = (r / nh) & (Ss - 1);
    float2* p = (float2*)t + (size_t)r * 64 + j;
    float2 v = *p;
    float c  = g_cos[(s << 6) + j];
    float sn = g_sin[(s << 6) + j];
    float2 o;
    o.x = v.x * c - v.y * sn;
    o.y = v.x * sn + v.y * c;
    *p = o;
}

// ---------------- Flash-style sliding-window attention -----------------------
#define STR 132
#define ATT_SMEM ((2*64*STR + 64*64 + 3*64) * 4)

__global__ __launch_bounds__(256) void attn_kernel() {
    extern __shared__ float sm[];
    float* Qs = sm;                 // [64][132]
    float* KV = sm + 64 * STR;      // [64][132] (K then V)
    float* Ps = sm + 2 * 64 * STR;  // [64][64]
    float* Mr = Ps + 64 * 64;
    float* Lr = Mr + 64;
    float* Al = Lr + 64;

    int t  = threadIdx.x;
    int tx = t & 15, ty = t >> 4;
    int b = blockIdx.z, h = blockIdx.y;
    int s0 = blockIdx.x << 6;
    int kh = h >> 2;                // GQA: 4 q-heads per kv-head

    const float* qb = g_q + ((size_t)((b * Ss + s0) * Hh + h)) * HDd;
    #pragma unroll
    for (int it = 0; it < 8; ++it) {
        int idx = t + (it << 8);
        int row = idx >> 5, d4 = (idx & 31) << 2;
        *(float4*)&Qs[row * STR + d4] =
            *(const float4*)(qb + (size_t)row * (Hh * HDd) + d4);
    }
    if (t < 64) { Mr[t] = -3.0e38f; Lr[t] = 0.0f; }

    float o[4][8];
    #pragma unroll
    for (int i = 0; i < 4; i++)
        #pragma unroll
        for (int dd = 0; dd < 8; dd++) o[i][dd] = 0.f;
    __syncthreads();

    const float SCALE = 0.08838834764831845f; // 1/sqrt(128)

    for (int c = 0; c < 9; ++c) {
        int cs = s0 - Ww + (c << 6);
        if (cs < 0) continue;

        const float* kb = g_k + ((size_t)((b * Ss + cs) * KHh + kh)) * HDd;
        #pragma unroll
        for (int it = 0; it < 8; ++it) {
            int idx = t + (it << 8);
            int row = idx >> 5, d4 = (idx & 31) << 2;
            *(float4*)&KV[row * STR + d4] =
                *(const float4*)(kb + (size_t)row * (KHh * HDd) + d4);
        }
        __syncthreads();

        float sc[4][4];
        #pragma unroll
        for (int i = 0; i < 4; i++)
            #pragma unroll
            for (int j = 0; j < 4; j++) sc[i][j] = 0.f;
        #pragma unroll 4
        for (int d = 0; d < 128; ++d) {
            float aq[4], bk[4];
            #pragma unroll
            for (int i = 0; i < 4; i++) aq[i] = Qs[(ty + (i << 4)) * STR + d];
            #pragma unroll
            for (int j = 0; j < 4; j++) bk[j] = KV[(tx + (j << 4)) * STR + d];
            #pragma unroll
            for (int i = 0; i < 4; i++)
                #pragma unroll
                for (int j = 0; j < 4; j++)
                    sc[i][j] += aq[i] * bk[j];
        }
        #pragma unroll
        for (int i = 0; i < 4; i++)
            #pragma unroll
            for (int j = 0; j < 4; j++) {
                int r = ty + (i << 4), ci = tx + (j << 4);
                int del = (s0 + r) - (cs + ci);
                Ps[(r << 6) + ci] =
                    (del >= 0 && del <= Ww) ? sc[i][j] * SCALE : -1.0e30f;
            }
        __syncthreads();

        {
            int row = t >> 2, part = t & 3;
            float* pr = Ps + (row << 6) + (part << 4);
            float mx = -3.0e38f;
            #pragma unroll
            for (int q = 0; q < 16; q++) mx = fmaxf(mx, pr[q]);
            mx = fmaxf(mx, __shfl_xor_sync(0xffffffffu, mx, 1));
            mx = fmaxf(mx, __shfl_xor_sync(0xffffffffu, mx, 2));
            float mold = Mr[row];
            float mnew = fmaxf(mold, mx);
            float ssum = 0.f;
            #pragma unroll
            for (int q = 0; q < 16; q++) {
                float pv = expf(pr[q] - mnew);
                pr[q] = pv;
                ssum += pv;
            }
            ssum += __shfl_xor_sync(0xffffffffu, ssum, 1);
            ssum += __shfl_xor_sync(0xffffffffu, ssum, 2);
            if (part == 0) {
                float al = expf(mold - mnew);
                Mr[row] = mnew;
                Lr[row] = Lr[row] * al + ssum;
                Al[row] = al;
            }
        }
        __syncthreads();

        const float* vb = g_v + ((size_t)((b * Ss + cs) * KHh + kh)) * HDd;
        #pragma unroll
        for (int it = 0; it < 8; ++it) {
            int idx = t + (it << 8);
            int row = idx >> 5, d4 = (idx & 31) << 2;
            *(float4*)&KV[row * STR + d4] =
                *(const float4*)(vb + (size_t)row * (KHh * HDd) + d4);
        }
        __syncthreads();

        float alv[4];
        #pragma unroll
        for (int i = 0; i < 4; i++) alv[i] = Al[ty + (i << 4)];
        #pragma unroll
        for (int i = 0; i < 4; i++)
            #pragma unroll
            for (int dd = 0; dd < 8; dd++) o[i][dd] *= alv[i];
        #pragma unroll 2
        for (int j = 0; j < 64; ++j) {
            float pv[4];
            #pragma unroll
            for (int i = 0; i < 4; i++) pv[i] = Ps[((ty + (i << 4)) << 6) + j];
            float vv[8];
            *(float4*)&vv[0] = *(float4*)&KV[j * STR + (tx << 3)];
            *(float4*)&vv[4] = *(float4*)&KV[j * STR + (tx << 3) + 4];
            #pragma unroll
            for (int i = 0; i < 4; i++)
                #pragma unroll
                for (int dd = 0; dd < 8; dd++)
                    o[i][dd] += pv[i] * vv[dd];
        }
        __syncthreads();
    }

    #pragma unroll
    for (int i = 0; i < 4; i++) {
        int r = ty + (i << 4);
        float inv = 1.0f / Lr[r];
        float* ob = g_att + ((size_t)(b * Ss + s0 + r)) * Dd + (h << 7) + (tx << 3);
        float4 u0 = {o[i][0]*inv, o[i][1]*inv, o[i][2]*inv, o[i][3]*inv};
        float4 u1 = {o[i][4]*inv, o[i][5]*inv, o[i][6]*inv, o[i][7]*inv};
        *(float4*)ob       = u0;
        *(float4*)(ob + 4) = u1;
    }
}

// ---------------- host launcher ---------------------------------------------
extern "C" void kernel_launch(void* const* d_in, const int* in_sizes, int n_in,
                              void* d_out, int out_size) {
    (void)in_sizes; (void)n_in; (void)out_size;
    const float* x   = (const float*)d_in[0];
    const float* lnw = (const float*)d_in[1];
    const float* wq  = (const float*)d_in[2];
    const float* wk  = (const float*)d_in[3];
    const float* wv  = (const float*)d_in[4];
    const float* wo  = (const float*)d_in[5];
    float* out = (float*)d_out;

    void *pxn, *pq, *pk, *pv, *patt;
    void *pxnh, *pxnl, *path, *patl;
    void *pwqh, *pwql, *pwkh, *pwkl, *pwvh, *pwvl, *pwoh, *pwol;
    cudaGetSymbolAddress(&pxn,  g_xn);
    cudaGetSymbolAddress(&pq,   g_q);
    cudaGetSymbolAddress(&pk,   g_k);
    cudaGetSymbolAddress(&pv,   g_v);
    cudaGetSymbolAddress(&patt, g_att);
    cudaGetSymbolAddress(&pxnh, g_xnh);
    cudaGetSymbolAddress(&pxnl, g_xnl);
    cudaGetSymbolAddress(&path, g_ath);
    cudaGetSymbolAddress(&patl, g_atl);
    cudaGetSymbolAddress(&pwqh, g_wqh);
    cudaGetSymbolAddress(&pwql, g_wql);
    cudaGetSymbolAddress(&pwkh, g_wkh);
    cudaGetSymbolAddress(&pwkl, g_wkl);
    cudaGetSymbolAddress(&pwvh, g_wvh);
    cudaGetSymbolAddress(&pwvl, g_wvl);
    cudaGetSymbolAddress(&pwoh, g_woh);
    cudaGetSymbolAddress(&pwol, g_wol);

    cudaFuncSetAttribute(attn_kernel,
                         cudaFuncAttributeMaxDynamicSharedMemorySize, ATT_SMEM);
    cudaFuncSetAttribute(gemm_bf16x3,
                         cudaFuncAttributeMaxDynamicSharedMemorySize, GSMEM_TOTAL);

    // 1) RMSNorm
    rms_kernel<<<NROW, 256>>>(x, lnw);
    // 2) split xn -> bf16 hi/lo
    split_kernel<<<(NROW * Dd / 4) / 256, 256>>>((const float*)pxn,
        (__nv_bfloat16*)pxnh, (__nv_bfloat16*)pxnl);
    // 3) split+transpose weights
    wsplitT_kernel<<<dim3(Dd/32,  Dd/32), 256>>>(wq, (__nv_bfloat16*)pwqh, (__nv_bfloat16*)pwql, Dd, Dd);
    wsplitT_kernel<<<dim3(KVD/32, Dd/32), 256>>>(wk, (__nv_bfloat16*)pwkh, (__nv_bfloat16*)pwkl, Dd, KVD);
    wsplitT_kernel<<<dim3(KVD/32, Dd/32), 256>>>(wv, (__nv_bfloat16*)pwvh, (__nv_bfloat16*)pwvl, Dd, KVD);
    wsplitT_kernel<<<dim3(Dd/32,  Dd/32), 256>>>(wo, (__nv_bfloat16*)pwoh, (__nv_bfloat16*)pwol, Dd, Dd);
    // 4) Q/K/V projections (mma.sync bf16x3)
    gemm_bf16x3<<<dim3(Dd/GBN,  NROW/GBM), 256, GSMEM_TOTAL>>>(
        (const __nv_bfloat16*)pxnh, (const __nv_bfloat16*)pxnl,
        (const __nv_bfloat16*)pwqh, (const __nv_bfloat16*)pwql, (float*)pq,  Dd,  Dd);
    gemm_bf16x3<<<dim3(KVD/GBN, NROW/GBM), 256, GSMEM_TOTAL>>>(
        (const __nv_bfloat16*)pxnh, (const __nv_bfloat16*)pxnl,
        (const __nv_bfloat16*)pwkh, (const __nv_bfloat16*)pwkl, (float*)pk,  KVD, Dd);
    gemm_bf16x3<<<dim3(KVD/GBN, NROW/GBM), 256, GSMEM_TOTAL>>>(
        (const __nv_bfloat16*)pxnh, (const __nv_bfloat16*)pxnl,
        (const __nv_bfloat16*)pwvh, (const __nv_bfloat16*)pwvl, (float*)pv,  KVD, Dd);
    // 5) RoPE
    rope_table_kernel<<<(Ss * 64) / 256, 256>>>();
    rope_apply_kernel<<<(Bb * Ss * Hh  * 64) / 256, 256>>>((float*)pq, Hh);
    rope_apply_kernel<<<(Bb * Ss * KHh * 64) / 256, 256>>>((float*)pk, KHh);
    // 6) Sliding-window attention
    attn_kernel<<<dim3(Ss / 64, Hh, Bb), 256, ATT_SMEM>>>();
    // 7) split attention output, then output projection (mma.sync bf16x3)
    split_kernel<<<(NROW * Dd / 4) / 256, 256>>>((const float*)patt,
        (__nv_bfloat16*)path, (__nv_bfloat16*)patl);
    gemm_bf16x3<<<dim3(Dd/GBN, NROW/GBM), 256, GSMEM_TOTAL>>>(
        (const __nv_bfloat16*)path, (const __nv_bfloat16*)patl,
        (const __nv_bfloat16*)pwoh, (const __nv_bfloat16*)pwol, out, Dd, Dd);
}